// round 12
// baseline (speedup 1.0000x reference)
#include <cuda_runtime.h>

#define NEG_SLOPE 0.2f
#define MAXN 100000
#define MAXE 3200000
#define EPT 2          // edges per thread in edge passes

static __device__ __forceinline__ float lrelu(float v) {
    return v > 0.f ? v : NEG_SLOPE * v;
}

static __device__ __forceinline__ void red_add_v2(float* addr, float a, float b) {
    asm volatile("red.global.add.v2.f32 [%0], {%1,%2};" :: "l"(addr), "f"(a), "f"(b) : "memory");
}
static __device__ __forceinline__ void red_add_v4(float* addr, float a, float b, float c, float d) {
    asm volatile("red.global.add.v4.f32 [%0], {%1,%2,%3,%4};"
                 :: "l"(addr), "f"(a), "f"(b), "f"(c), "f"(d) : "memory");
}

static __device__ __forceinline__ float dot3(float4 v, float4 c) {
    return v.x * c.x + v.y * c.y + v.z * c.z;
}

// ---------------- scratch (device globals; no runtime allocation) ----------------
__device__ int g_is64;
__device__ __align__(16) int2 g_sd[MAXE];    // packed (src,dst): only used when input is int64

// Layer-1: per-node state is x (float4, 1 sector). Scores are linear in x.
__device__ __align__(16) float4 g_X[MAXN];
__device__ float4 g_csf, g_cdf, g_csr, g_cdr;   // W1@as1, W1@ad1, W1r@as1r, W1r@ad1r
// Accumulators: (sum w*x0, w*x1, w*x2, sum w)
__device__ __align__(16) float4 g_accf[MAXN];
__device__ __align__(16) float4 g_accr[MAXN];

// Layer-2: per-node state is (h2f, h2r).
__device__ __align__(16) float2 g_H[MAXN];
__device__ __align__(16) float2 g_nd2f[MAXN];
__device__ __align__(16) float2 g_nd2r[MAXN];

// ---------------- layer 1 node prep (+ fused prolog: coefficients & dtype flag) ----------------
__global__ void k_node1(const float* __restrict__ x,
                        const float* __restrict__ W1,  const float* __restrict__ as1,
                        const float* __restrict__ ad1,
                        const float* __restrict__ W1r, const float* __restrict__ as1r,
                        const float* __restrict__ ad1r,
                        const int* __restrict__ ei32, int N) {
    __shared__ float4 s_c[4];    // csf, cdf, csr, cdr

    // block 0, warp 1: int64-vs-int32 detection on first 32 odd words (int64
    // node ids < 2^31 have zero high words; 32 consecutive zeros from genuine
    // int32 ids uniform in [0,1e5) has probability ~(1/46)^32 ~ 0).
    if (blockIdx.x == 0 && threadIdx.x >= 32 && threadIdx.x < 64) {
        unsigned ballot = __ballot_sync(0xFFFFFFFFu, ei32[1 + 2 * (threadIdx.x - 32)] != 0);
        if (threadIdx.x == 32) g_is64 = (ballot == 0u) ? 1 : 0;
    }

    // thread 0 of every block: score-coefficient vectors (uniform; ~200 cyc,
    // hidden behind the block's other warps). Block 0 publishes for edge1.
    if (threadIdx.x == 0) {
        float csf[3] = {0,0,0}, cdf[3] = {0,0,0}, csr[3] = {0,0,0}, cdr[3] = {0,0,0};
#pragma unroll
        for (int f = 0; f < 16; f++) {
            float a1 = __ldg(&as1[f]),  a2 = __ldg(&ad1[f]);
            float a3 = __ldg(&as1r[f]), a4 = __ldg(&ad1r[f]);
#pragma unroll
            for (int k = 0; k < 3; k++) {
                float w  = __ldg(&W1[16 * k + f]);
                float wr = __ldg(&W1r[16 * k + f]);
                csf[k] += w * a1;  cdf[k] += w * a2;
                csr[k] += wr * a3; cdr[k] += wr * a4;
            }
        }
        s_c[0] = make_float4(csf[0], csf[1], csf[2], 0.f);
        s_c[1] = make_float4(cdf[0], cdf[1], cdf[2], 0.f);
        s_c[2] = make_float4(csr[0], csr[1], csr[2], 0.f);
        s_c[3] = make_float4(cdr[0], cdr[1], cdr[2], 0.f);
        if (blockIdx.x == 0) {
            g_csf = s_c[0]; g_cdf = s_c[1]; g_csr = s_c[2]; g_cdr = s_c[3];
        }
    }
    __syncthreads();

    int i = blockIdx.x * blockDim.x + threadIdx.x;
    if (i >= N) return;
    float x0 = x[3 * i], x1 = x[3 * i + 1], x2 = x[3 * i + 2];
    float4 X = make_float4(x0, x1, x2, 0.f);

    float ssf = dot3(X, s_c[0]), sdf = dot3(X, s_c[1]);
    float ssr = dot3(X, s_c[2]), sdr = dot3(X, s_c[3]);

    g_X[i] = X;
    // self-loop contribution
    float wf = __expf(lrelu(ssf + sdf));
    float wr = __expf(lrelu(ssr + sdr));
    g_accf[i] = make_float4(wf * x0, wf * x1, wf * x2, wf);
    g_accr[i] = make_float4(wr * x0, wr * x1, wr * x2, wr);
}

// ---------------- layer 1 edge pass: 2 gathers + 2 REDs per edge ----------------
__global__ void __launch_bounds__(256) k_edge1(const void* __restrict__ ei, int E) {
    bool is64 = (g_is64 != 0);

    int t = blockIdx.x * blockDim.x + threadIdx.x;
    int j0 = t * EPT;
    if (j0 >= E) return;
    int n = E - j0; if (n > EPT) n = EPT;

    float4 csf = g_csf, cdf = g_cdf, csr = g_csr, cdr = g_cdr;

    int s[EPT], d[EPT];
    if (is64) {
        const long long* p = (const long long*)ei;
#pragma unroll
        for (int u = 0; u < EPT; u++) if (u < n) { s[u] = (int)p[j0 + u]; d[u] = (int)p[E + j0 + u]; }
        // materialize int32 pairs for edge2 (skipped for int32 input, which
        // edge2 can read directly at the same cost)
#pragma unroll
        for (int u = 0; u < EPT; u++) if (u < n) g_sd[j0 + u] = make_int2(s[u], d[u]);
    } else {
        const int* p = (const int*)ei;
#pragma unroll
        for (int u = 0; u < EPT; u++) if (u < n) { s[u] = p[j0 + u]; d[u] = p[E + j0 + u]; }
    }

    float4 Xs[EPT], Xd[EPT];
#pragma unroll
    for (int u = 0; u < EPT; u++) if (u < n) {
        Xs[u] = g_X[s[u]];
        Xd[u] = g_X[d[u]];
    }
#pragma unroll
    for (int u = 0; u < EPT; u++) if (u < n) {
        // forward edge s->d: exp(lrelu(ssf[s] + sdf[d])) -> accf[d]
        float wf = __expf(lrelu(dot3(Xs[u], csf) + dot3(Xd[u], cdf)));
        // reverse edge d->s: exp(lrelu(ssr[d] + sdr[s])) -> accr[s]
        float wr = __expf(lrelu(dot3(Xd[u], csr) + dot3(Xs[u], cdr)));
        red_add_v4((float*)&g_accf[d[u]], wf * Xs[u].x, wf * Xs[u].y, wf * Xs[u].z, wf);
        red_add_v4((float*)&g_accr[s[u]], wr * Xd[u].x, wr * Xd[u].y, wr * Xd[u].z, wr);
    }
}

// ---------------- layer 2 node prep: direction-split (blockIdx.y = 0 fwd, 1 rev) ----------------
__global__ void k_node2(const float* __restrict__ W1, const float* __restrict__ b1,
                        const float* __restrict__ W2,
                        const float* __restrict__ as2, const float* __restrict__ ad2,
                        const float* __restrict__ W1r, const float* __restrict__ b1r,
                        const float* __restrict__ W2r,
                        const float* __restrict__ as2r, const float* __restrict__ ad2r, int N) {
    int i = blockIdx.x * blockDim.x + threadIdx.x;
    if (i >= N) return;
    bool rev = (blockIdx.y != 0);

    const float4* Wv = (const float4*)(rev ? W1r : W1);   // [3][4] float4s
    const float4* bv = (const float4*)(rev ? b1r : b1);
    const float4* Ov = (const float4*)(rev ? W2r : W2);

    float4 a = rev ? g_accr[i] : g_accf[i];
    float inv = 1.f / (a.w + 1e-16f);
    float n0 = a.x * inv, n1 = a.y * inv, n2 = a.z * inv;

    float h2 = 0.f;
#pragma unroll
    for (int q = 0; q < 4; q++) {
        float4 w0 = __ldg(&Wv[q]), w1 = __ldg(&Wv[4 + q]), w2 = __ldg(&Wv[8 + q]);
        float4 bb = __ldg(&bv[q]), wo = __ldg(&Ov[q]);
        h2 += fmaxf(n0 * w0.x + n1 * w1.x + n2 * w2.x + bb.x, 0.f) * wo.x;
        h2 += fmaxf(n0 * w0.y + n1 * w1.y + n2 * w2.y + bb.y, 0.f) * wo.y;
        h2 += fmaxf(n0 * w0.z + n1 * w1.z + n2 * w2.z + bb.z, 0.f) * wo.z;
        h2 += fmaxf(n0 * w0.w + n1 * w1.w + n2 * w2.w + bb.w, 0.f) * wo.w;
    }
    // write this direction's half of the interleaved per-node pack
    ((float*)&g_H[i])[rev ? 1 : 0] = h2;

    float sum2 = rev ? (__ldg(&as2r[0]) + __ldg(&ad2r[0]))
                     : (__ldg(&as2[0])  + __ldg(&ad2[0]));
    float w = __expf(lrelu(h2 * sum2));
    if (rev) g_nd2r[i] = make_float2(w * h2, w);
    else     g_nd2f[i] = make_float2(w * h2, w);
}

// ---------------- layer 2 edge pass: 2 gathers + 2 REDs per edge ----------------
__global__ void __launch_bounds__(256) k_edge2(const void* __restrict__ ei,
                                               const float* __restrict__ as2,
                                               const float* __restrict__ ad2,
                                               const float* __restrict__ as2r,
                                               const float* __restrict__ ad2r, int E) {
    bool is64 = (g_is64 != 0);
    float a2s = __ldg(&as2[0]),  a2d = __ldg(&ad2[0]);
    float a2sr = __ldg(&as2r[0]), a2dr = __ldg(&ad2r[0]);

    int t = blockIdx.x * blockDim.x + threadIdx.x;
    int j0 = t * EPT;
    if (j0 >= E) return;
    int n = E - j0; if (n > EPT) n = EPT;

    int s[EPT], d[EPT];
    if (is64) {
#pragma unroll
        for (int u = 0; u < EPT; u++) if (u < n) {
            int2 sd = g_sd[j0 + u];
            s[u] = sd.x; d[u] = sd.y;
        }
    } else {
        const int* p = (const int*)ei;
#pragma unroll
        for (int u = 0; u < EPT; u++) if (u < n) { s[u] = p[j0 + u]; d[u] = p[E + j0 + u]; }
    }

    float2 Hs[EPT], Hd[EPT];
#pragma unroll
    for (int u = 0; u < EPT; u++) if (u < n) {
        Hs[u] = g_H[s[u]];
        Hd[u] = g_H[d[u]];
    }
#pragma unroll
    for (int u = 0; u < EPT; u++) if (u < n) {
        // forward s->d: score = h2f[s]*as2 + h2f[d]*ad2
        float wf = __expf(lrelu(Hs[u].x * a2s + Hd[u].x * a2d));
        // reverse d->s: score = h2r[d]*as2r + h2r[s]*ad2r
        float wr = __expf(lrelu(Hd[u].y * a2sr + Hs[u].y * a2dr));
        red_add_v2((float*)&g_nd2f[d[u]], wf * Hs[u].x, wf);
        red_add_v2((float*)&g_nd2r[s[u]], wr * Hd[u].y, wr);
    }
}

// ---------------- final combine (2 nodes/thread, vectorized) ----------------
__global__ void k_out(float* __restrict__ out, const float* __restrict__ b2,
                      const float* __restrict__ b2r, int N) {
    int t = blockIdx.x * blockDim.x + threadIdx.x;
    int i = 2 * t;
    if (i >= N) return;
    float bf = __ldg(&b2[0]), br = __ldg(&b2r[0]);
    float4 f = ((const float4*)g_nd2f)[t];   // nd2f[i], nd2f[i+1]
    float4 r = ((const float4*)g_nd2r)[t];
    float o0 = 0.5f * (f.x / (f.y + 1e-16f) + bf + r.x / (r.y + 1e-16f) + br);
    if (i + 1 < N) {
        float o1 = 0.5f * (f.z / (f.w + 1e-16f) + bf + r.z / (r.w + 1e-16f) + br);
        *(float2*)&out[i] = make_float2(o0, o1);
    } else {
        out[i] = o0;
    }
}

extern "C" void kernel_launch(void* const* d_in, const int* in_sizes, int n_in,
                              void* d_out, int out_size) {
    const float* x   = (const float*)d_in[0];
    const void*  ei  = d_in[1];
    const float* W1  = (const float*)d_in[2];
    const float* as1 = (const float*)d_in[3];
    const float* ad1 = (const float*)d_in[4];
    const float* b1  = (const float*)d_in[5];
    const float* W2  = (const float*)d_in[6];
    const float* as2 = (const float*)d_in[7];
    const float* ad2 = (const float*)d_in[8];
    const float* b2  = (const float*)d_in[9];
    const float* W1r  = (const float*)d_in[10];
    const float* as1r = (const float*)d_in[11];
    const float* ad1r = (const float*)d_in[12];
    const float* b1r  = (const float*)d_in[13];
    const float* W2r  = (const float*)d_in[14];
    const float* as2r = (const float*)d_in[15];
    const float* ad2r = (const float*)d_in[16];
    const float* b2r  = (const float*)d_in[17];

    int N = in_sizes[0] / 3;
    int E = in_sizes[1] / 2;

    const int TB = 256;
    int nbN = (N + TB - 1) / TB;
    int nbE = (E + TB * EPT - 1) / (TB * EPT);
    int nbO = (N + TB * 2 - 1) / (TB * 2);

    dim3 grid2(nbN, 2);

    k_node1<<<nbN, TB>>>(x, W1, as1, ad1, W1r, as1r, ad1r, (const int*)ei, N);
    k_edge1<<<nbE, TB>>>(ei, E);
    k_node2<<<grid2, TB>>>(W1, b1, W2, as2, ad2, W1r, b1r, W2r, as2r, ad2r, N);
    k_edge2<<<nbE, TB>>>(ei, as2, ad2, as2r, ad2r, E);
    k_out<<<nbO, TB>>>((float*)d_out, b2, b2r, N);
}

// round 13
// speedup vs baseline: 1.0179x; 1.0179x over previous
#include <cuda_runtime.h>

#define NEG_SLOPE 0.2f
#define MAXN 100000
#define MAXE 3200000
#define EPT 2          // edges per thread in edge passes

static __device__ __forceinline__ float lrelu(float v) {
    return v > 0.f ? v : NEG_SLOPE * v;
}

static __device__ __forceinline__ void red_add_v2(float* addr, float a, float b) {
    asm volatile("red.global.add.v2.f32 [%0], {%1,%2};" :: "l"(addr), "f"(a), "f"(b) : "memory");
}
static __device__ __forceinline__ void red_add_v4(float* addr, float a, float b, float c, float d) {
    asm volatile("red.global.add.v4.f32 [%0], {%1,%2,%3,%4};"
                 :: "l"(addr), "f"(a), "f"(b), "f"(c), "f"(d) : "memory");
}

static __device__ __forceinline__ float dot3(float4 v, float4 c) {
    return v.x * c.x + v.y * c.y + v.z * c.z;
}

// ---------------- scratch (device globals; no runtime allocation) ----------------
__device__ int g_is64;
__device__ __align__(16) int2 g_sd[MAXE];    // packed (src,dst): only used when input is int64

// Layer-1: per-node state is x (float4, 1 sector). Scores are linear in x.
__device__ __align__(16) float4 g_X[MAXN];
__device__ float4 g_csf, g_cdf, g_csr, g_cdr;   // W1@as1, W1@ad1, W1r@as1r, W1r@ad1r
// Accumulators: (sum w*x0, w*x1, w*x2, sum w)
__device__ __align__(16) float4 g_accf[MAXN];
__device__ __align__(16) float4 g_accr[MAXN];

// Layer-2: per-node state is (h2f, h2r).
__device__ __align__(16) float2 g_H[MAXN];
__device__ __align__(16) float2 g_nd2f[MAXN];
__device__ __align__(16) float2 g_nd2r[MAXN];

// ---------------- prolog: score coefficients + edge dtype detection ----------------
__global__ void k_pre(const float* __restrict__ W1,  const float* __restrict__ as1,
                      const float* __restrict__ ad1,
                      const float* __restrict__ W1r, const float* __restrict__ as1r,
                      const float* __restrict__ ad1r,
                      const int* __restrict__ ei32) {
    // lanes 0..31: int64-vs-int32 detection on first 32 odd words (int64 node
    // ids < 2^31 have zero high words; 32 consecutive zeros from genuine
    // int32 ids uniform in [0,1e5) has probability ~(1/46)^32 ~ 0).
    unsigned ballot = __ballot_sync(0xFFFFFFFFu, ei32[1 + 2 * threadIdx.x] != 0);
    if (threadIdx.x == 0) {
        g_is64 = (ballot == 0u) ? 1 : 0;
        float csf[3] = {0,0,0}, cdf[3] = {0,0,0}, csr[3] = {0,0,0}, cdr[3] = {0,0,0};
        for (int f = 0; f < 16; f++) {
            for (int k = 0; k < 3; k++) {
                float w  = W1[16 * k + f];
                float wr = W1r[16 * k + f];
                csf[k] += w * as1[f];   cdf[k] += w * ad1[f];
                csr[k] += wr * as1r[f]; cdr[k] += wr * ad1r[f];
            }
        }
        g_csf = make_float4(csf[0], csf[1], csf[2], 0.f);
        g_cdf = make_float4(cdf[0], cdf[1], cdf[2], 0.f);
        g_csr = make_float4(csr[0], csr[1], csr[2], 0.f);
        g_cdr = make_float4(cdr[0], cdr[1], cdr[2], 0.f);
    }
}

// ---------------- layer 1 node prep ----------------
__global__ void k_node1(const float* __restrict__ x, int N) {
    int i = blockIdx.x * blockDim.x + threadIdx.x;
    if (i >= N) return;
    float4 csf = g_csf, cdf = g_cdf, csr = g_csr, cdr = g_cdr;
    float x0 = x[3 * i], x1 = x[3 * i + 1], x2 = x[3 * i + 2];
    float4 X = make_float4(x0, x1, x2, 0.f);

    float ssf = dot3(X, csf), sdf = dot3(X, cdf);
    float ssr = dot3(X, csr), sdr = dot3(X, cdr);

    g_X[i] = X;
    // self-loop contribution
    float wf = __expf(lrelu(ssf + sdf));
    float wr = __expf(lrelu(ssr + sdr));
    g_accf[i] = make_float4(wf * x0, wf * x1, wf * x2, wf);
    g_accr[i] = make_float4(wr * x0, wr * x1, wr * x2, wr);
}

// ---------------- layer 1 edge pass: 2 gathers + 2 REDs per edge ----------------
__global__ void __launch_bounds__(256) k_edge1(const void* __restrict__ ei, int E) {
    bool is64 = (g_is64 != 0);

    int t = blockIdx.x * blockDim.x + threadIdx.x;
    int j0 = t * EPT;
    if (j0 >= E) return;
    int n = E - j0; if (n > EPT) n = EPT;

    float4 csf = g_csf, cdf = g_cdf, csr = g_csr, cdr = g_cdr;

    int s[EPT], d[EPT];
    if (is64) {
        const long long* p = (const long long*)ei;
#pragma unroll
        for (int u = 0; u < EPT; u++) if (u < n) { s[u] = (int)p[j0 + u]; d[u] = (int)p[E + j0 + u]; }
        // materialize int32 pairs for edge2 (skipped for int32 input, which
        // edge2 can read directly at the same cost)
#pragma unroll
        for (int u = 0; u < EPT; u++) if (u < n) g_sd[j0 + u] = make_int2(s[u], d[u]);
    } else {
        const int* p = (const int*)ei;
#pragma unroll
        for (int u = 0; u < EPT; u++) if (u < n) { s[u] = p[j0 + u]; d[u] = p[E + j0 + u]; }
    }

    float4 Xs[EPT], Xd[EPT];
#pragma unroll
    for (int u = 0; u < EPT; u++) if (u < n) {
        Xs[u] = g_X[s[u]];
        Xd[u] = g_X[d[u]];
    }
#pragma unroll
    for (int u = 0; u < EPT; u++) if (u < n) {
        // forward edge s->d: exp(lrelu(ssf[s] + sdf[d])) -> accf[d]
        float wf = __expf(lrelu(dot3(Xs[u], csf) + dot3(Xd[u], cdf)));
        // reverse edge d->s: exp(lrelu(ssr[d] + sdr[s])) -> accr[s]
        float wr = __expf(lrelu(dot3(Xd[u], csr) + dot3(Xs[u], cdr)));
        red_add_v4((float*)&g_accf[d[u]], wf * Xs[u].x, wf * Xs[u].y, wf * Xs[u].z, wf);
        red_add_v4((float*)&g_accr[s[u]], wr * Xd[u].x, wr * Xd[u].y, wr * Xd[u].z, wr);
    }
}

// ---------------- layer 2 node prep: direction-split (blockIdx.y = 0 fwd, 1 rev) ----------------
// h2 = relu(acc/den @ W1 + b1) @ W2 = (1/den) * sum relu(acc@W1col + den*b1col)*W2col
// (valid since den > 0); the reciprocal overlaps the FMA loop instead of gating it.
__global__ void k_node2(const float* __restrict__ W1, const float* __restrict__ b1,
                        const float* __restrict__ W2,
                        const float* __restrict__ as2, const float* __restrict__ ad2,
                        const float* __restrict__ W1r, const float* __restrict__ b1r,
                        const float* __restrict__ W2r,
                        const float* __restrict__ as2r, const float* __restrict__ ad2r, int N) {
    int i = blockIdx.x * blockDim.x + threadIdx.x;
    if (i >= N) return;
    bool rev = (blockIdx.y != 0);

    const float4* Wv = (const float4*)(rev ? W1r : W1);   // [3][4] float4s
    const float4* bv = (const float4*)(rev ? b1r : b1);
    const float4* Ov = (const float4*)(rev ? W2r : W2);

    float4 a = rev ? g_accr[i] : g_accf[i];
    float den = a.w + 1e-16f;
    float inv = 1.f / den;                                // overlaps the loop below

    float acc = 0.f;
#pragma unroll
    for (int q = 0; q < 4; q++) {
        float4 w0 = __ldg(&Wv[q]), w1 = __ldg(&Wv[4 + q]), w2 = __ldg(&Wv[8 + q]);
        float4 bb = __ldg(&bv[q]), wo = __ldg(&Ov[q]);
        acc += fmaxf(a.x * w0.x + a.y * w1.x + a.z * w2.x + den * bb.x, 0.f) * wo.x;
        acc += fmaxf(a.x * w0.y + a.y * w1.y + a.z * w2.y + den * bb.y, 0.f) * wo.y;
        acc += fmaxf(a.x * w0.z + a.y * w1.z + a.z * w2.z + den * bb.z, 0.f) * wo.z;
        acc += fmaxf(a.x * w0.w + a.y * w1.w + a.z * w2.w + den * bb.w, 0.f) * wo.w;
    }
    float h2 = acc * inv;

    // write this direction's half of the interleaved per-node pack
    ((float*)&g_H[i])[rev ? 1 : 0] = h2;

    float sum2 = rev ? (__ldg(&as2r[0]) + __ldg(&ad2r[0]))
                     : (__ldg(&as2[0])  + __ldg(&ad2[0]));
    float w = __expf(lrelu(h2 * sum2));
    if (rev) g_nd2r[i] = make_float2(w * h2, w);
    else     g_nd2f[i] = make_float2(w * h2, w);
}

// ---------------- layer 2 edge pass: 2 gathers + 2 REDs per edge ----------------
__global__ void __launch_bounds__(256) k_edge2(const void* __restrict__ ei,
                                               const float* __restrict__ as2,
                                               const float* __restrict__ ad2,
                                               const float* __restrict__ as2r,
                                               const float* __restrict__ ad2r, int E) {
    bool is64 = (g_is64 != 0);
    float a2s = __ldg(&as2[0]),  a2d = __ldg(&ad2[0]);
    float a2sr = __ldg(&as2r[0]), a2dr = __ldg(&ad2r[0]);

    int t = blockIdx.x * blockDim.x + threadIdx.x;
    int j0 = t * EPT;
    if (j0 >= E) return;
    int n = E - j0; if (n > EPT) n = EPT;

    int s[EPT], d[EPT];
    if (is64) {
#pragma unroll
        for (int u = 0; u < EPT; u++) if (u < n) {
            int2 sd = g_sd[j0 + u];
            s[u] = sd.x; d[u] = sd.y;
        }
    } else {
        const int* p = (const int*)ei;
#pragma unroll
        for (int u = 0; u < EPT; u++) if (u < n) { s[u] = p[j0 + u]; d[u] = p[E + j0 + u]; }
    }

    float2 Hs[EPT], Hd[EPT];
#pragma unroll
    for (int u = 0; u < EPT; u++) if (u < n) {
        Hs[u] = g_H[s[u]];
        Hd[u] = g_H[d[u]];
    }
#pragma unroll
    for (int u = 0; u < EPT; u++) if (u < n) {
        // forward s->d: score = h2f[s]*as2 + h2f[d]*ad2
        float wf = __expf(lrelu(Hs[u].x * a2s + Hd[u].x * a2d));
        // reverse d->s: score = h2r[d]*as2r + h2r[s]*ad2r
        float wr = __expf(lrelu(Hd[u].y * a2sr + Hs[u].y * a2dr));
        red_add_v2((float*)&g_nd2f[d[u]], wf * Hs[u].x, wf);
        red_add_v2((float*)&g_nd2r[s[u]], wr * Hd[u].y, wr);
    }
}

// ---------------- final combine (2 nodes/thread, vectorized) ----------------
__global__ void k_out(float* __restrict__ out, const float* __restrict__ b2,
                      const float* __restrict__ b2r, int N) {
    int t = blockIdx.x * blockDim.x + threadIdx.x;
    int i = 2 * t;
    if (i >= N) return;
    float bf = __ldg(&b2[0]), br = __ldg(&b2r[0]);
    float4 f = ((const float4*)g_nd2f)[t];   // nd2f[i], nd2f[i+1]
    float4 r = ((const float4*)g_nd2r)[t];
    float o0 = 0.5f * (f.x / (f.y + 1e-16f) + bf + r.x / (r.y + 1e-16f) + br);
    if (i + 1 < N) {
        float o1 = 0.5f * (f.z / (f.w + 1e-16f) + bf + r.z / (r.w + 1e-16f) + br);
        *(float2*)&out[i] = make_float2(o0, o1);
    } else {
        out[i] = o0;
    }
}

extern "C" void kernel_launch(void* const* d_in, const int* in_sizes, int n_in,
                              void* d_out, int out_size) {
    const float* x   = (const float*)d_in[0];
    const void*  ei  = d_in[1];
    const float* W1  = (const float*)d_in[2];
    const float* as1 = (const float*)d_in[3];
    const float* ad1 = (const float*)d_in[4];
    const float* b1  = (const float*)d_in[5];
    const float* W2  = (const float*)d_in[6];
    const float* as2 = (const float*)d_in[7];
    const float* ad2 = (const float*)d_in[8];
    const float* b2  = (const float*)d_in[9];
    const float* W1r  = (const float*)d_in[10];
    const float* as1r = (const float*)d_in[11];
    const float* ad1r = (const float*)d_in[12];
    const float* b1r  = (const float*)d_in[13];
    const float* W2r  = (const float*)d_in[14];
    const float* as2r = (const float*)d_in[15];
    const float* ad2r = (const float*)d_in[16];
    const float* b2r  = (const float*)d_in[17];

    int N = in_sizes[0] / 3;
    int E = in_sizes[1] / 2;

    const int TB = 256;
    int nbN = (N + TB - 1) / TB;
    int nbE = (E + TB * EPT - 1) / (TB * EPT);
    int nbO = (N + TB * 2 - 1) / (TB * 2);

    dim3 grid2(nbN, 2);

    k_pre<<<1, 32>>>(W1, as1, ad1, W1r, as1r, ad1r, (const int*)ei);
    k_node1<<<nbN, TB>>>(x, N);
    k_edge1<<<nbE, TB>>>(ei, E);
    k_node2<<<grid2, TB>>>(W1, b1, W2, as2, ad2, W1r, b1r, W2r, as2r, ad2r, N);
    k_edge2<<<nbE, TB>>>(ei, as2, ad2, as2r, ad2r, E);
    k_out<<<nbO, TB>>>((float*)d_out, b2, b2r, N);
}

// round 14
// speedup vs baseline: 1.0328x; 1.0147x over previous
#include <cuda_runtime.h>

#define NEG_SLOPE 0.2f
#define MAXN 100000
#define MAXE 3200000
#define EPT 2          // edges per thread, edge1
#define EPT2 4         // edges per thread, edge2

static __device__ __forceinline__ float lrelu(float v) {
    return v > 0.f ? v : NEG_SLOPE * v;
}

static __device__ __forceinline__ void red_add_v2(float* addr, float a, float b) {
    asm volatile("red.global.add.v2.f32 [%0], {%1,%2};" :: "l"(addr), "f"(a), "f"(b) : "memory");
}
static __device__ __forceinline__ void red_add_v4(float* addr, float a, float b, float c, float d) {
    asm volatile("red.global.add.v4.f32 [%0], {%1,%2,%3,%4};"
                 :: "l"(addr), "f"(a), "f"(b), "f"(c), "f"(d) : "memory");
}

static __device__ __forceinline__ float dot3(float4 v, float4 c) {
    return v.x * c.x + v.y * c.y + v.z * c.z;
}

// ---------------- scratch (device globals; no runtime allocation) ----------------
__device__ int g_is64;
__device__ __align__(16) int2 g_sd[MAXE];    // packed (src,dst): only used when input is int64

// Layer-1: per-node state is x (float4, 1 sector). Scores are linear in x.
__device__ __align__(16) float4 g_X[MAXN];
__device__ float4 g_csf, g_cdf, g_csr, g_cdr;   // W1@as1, W1@ad1, W1r@as1r, W1r@ad1r
// Accumulators: (sum w*x0, w*x1, w*x2, sum w)
__device__ __align__(16) float4 g_accf[MAXN];
__device__ __align__(16) float4 g_accr[MAXN];

// Packed layer-2 weights per direction: [0..11]=W1 rows, [12..15]=b1, [16..19]=W2
__device__ __align__(16) float4 g_wpack[2][20];

// Layer-2: per-node state is (h2f, h2r).
__device__ __align__(16) float2 g_H[MAXN];
__device__ __align__(16) float2 g_nd2f[MAXN];
__device__ __align__(16) float2 g_nd2r[MAXN];

// ---------------- prolog: coefficients + dtype detection + weight packing ----------------
__global__ void k_pre(const float* __restrict__ W1,  const float* __restrict__ as1,
                      const float* __restrict__ ad1,
                      const float* __restrict__ W1r, const float* __restrict__ as1r,
                      const float* __restrict__ ad1r,
                      const float* __restrict__ b1,  const float* __restrict__ W2,
                      const float* __restrict__ b1r, const float* __restrict__ W2r,
                      const int* __restrict__ ei32) {
    int t = threadIdx.x;
    // warp 0: int64-vs-int32 detection on first 32 odd words (int64 node ids
    // < 2^31 have zero high words; 32 consecutive zeros from genuine int32
    // ids uniform in [0,1e5) has probability ~(1/46)^32 ~ 0).
    if (t < 32) {
        unsigned ballot = __ballot_sync(0xFFFFFFFFu, ei32[1 + 2 * t] != 0);
        if (t == 0) g_is64 = (ballot == 0u) ? 1 : 0;
    }
    // threads 32..191: pack layer-2 weights, 80 floats per direction
    if (t >= 32 && t < 192) {
        int idx = t - 32;            // 0..159
        int dir = idx / 80;          // 0 fwd, 1 rev
        int off = idx % 80;          // 0..79
        const float* srcW1 = dir ? W1r : W1;
        const float* srcb1 = dir ? b1r : b1;
        const float* srcW2 = dir ? W2r : W2;
        float v;
        if (off < 48)      v = srcW1[off];
        else if (off < 64) v = srcb1[off - 48];
        else               v = srcW2[off - 64];
        ((float*)g_wpack[dir])[off] = v;
    }
    // thread 0: layer-1 score coefficients
    if (t == 0) {
        float csf[3] = {0,0,0}, cdf[3] = {0,0,0}, csr[3] = {0,0,0}, cdr[3] = {0,0,0};
        for (int f = 0; f < 16; f++) {
            for (int k = 0; k < 3; k++) {
                float w  = W1[16 * k + f];
                float wr = W1r[16 * k + f];
                csf[k] += w * as1[f];   cdf[k] += w * ad1[f];
                csr[k] += wr * as1r[f]; cdr[k] += wr * ad1r[f];
            }
        }
        g_csf = make_float4(csf[0], csf[1], csf[2], 0.f);
        g_cdf = make_float4(cdf[0], cdf[1], cdf[2], 0.f);
        g_csr = make_float4(csr[0], csr[1], csr[2], 0.f);
        g_cdr = make_float4(cdr[0], cdr[1], cdr[2], 0.f);
    }
}

// ---------------- layer 1 node prep ----------------
__global__ void k_node1(const float* __restrict__ x, int N) {
    int i = blockIdx.x * blockDim.x + threadIdx.x;
    if (i >= N) return;
    float4 csf = g_csf, cdf = g_cdf, csr = g_csr, cdr = g_cdr;
    float x0 = x[3 * i], x1 = x[3 * i + 1], x2 = x[3 * i + 2];
    float4 X = make_float4(x0, x1, x2, 0.f);

    float ssf = dot3(X, csf), sdf = dot3(X, cdf);
    float ssr = dot3(X, csr), sdr = dot3(X, cdr);

    g_X[i] = X;
    // self-loop contribution
    float wf = __expf(lrelu(ssf + sdf));
    float wr = __expf(lrelu(ssr + sdr));
    g_accf[i] = make_float4(wf * x0, wf * x1, wf * x2, wf);
    g_accr[i] = make_float4(wr * x0, wr * x1, wr * x2, wr);
}

// ---------------- layer 1 edge pass: 2 gathers + 2 REDs per edge ----------------
__global__ void __launch_bounds__(256) k_edge1(const void* __restrict__ ei, int E) {
    bool is64 = (g_is64 != 0);

    int t = blockIdx.x * blockDim.x + threadIdx.x;
    int j0 = t * EPT;
    if (j0 >= E) return;
    int n = E - j0; if (n > EPT) n = EPT;

    float4 csf = g_csf, cdf = g_cdf, csr = g_csr, cdr = g_cdr;

    int s[EPT], d[EPT];
    if (is64) {
        const long long* p = (const long long*)ei;
#pragma unroll
        for (int u = 0; u < EPT; u++) if (u < n) { s[u] = (int)p[j0 + u]; d[u] = (int)p[E + j0 + u]; }
        // materialize int32 pairs for edge2 (skipped for int32 input, which
        // edge2 can read directly at the same cost)
#pragma unroll
        for (int u = 0; u < EPT; u++) if (u < n) g_sd[j0 + u] = make_int2(s[u], d[u]);
    } else {
        const int* p = (const int*)ei;
#pragma unroll
        for (int u = 0; u < EPT; u++) if (u < n) { s[u] = p[j0 + u]; d[u] = p[E + j0 + u]; }
    }

    float4 Xs[EPT], Xd[EPT];
#pragma unroll
    for (int u = 0; u < EPT; u++) if (u < n) {
        Xs[u] = g_X[s[u]];
        Xd[u] = g_X[d[u]];
    }
#pragma unroll
    for (int u = 0; u < EPT; u++) if (u < n) {
        // forward edge s->d: exp(lrelu(ssf[s] + sdf[d])) -> accf[d]
        float wf = __expf(lrelu(dot3(Xs[u], csf) + dot3(Xd[u], cdf)));
        // reverse edge d->s: exp(lrelu(ssr[d] + sdr[s])) -> accr[s]
        float wr = __expf(lrelu(dot3(Xd[u], csr) + dot3(Xs[u], cdr)));
        red_add_v4((float*)&g_accf[d[u]], wf * Xs[u].x, wf * Xs[u].y, wf * Xs[u].z, wf);
        red_add_v4((float*)&g_accr[s[u]], wr * Xd[u].x, wr * Xd[u].y, wr * Xd[u].z, wr);
    }
}

// ---------------- layer 2 node prep: direction-split (blockIdx.y = 0 fwd, 1 rev) ----------------
// h2 = relu(acc/den @ W1 + b1) @ W2 = (1/den) * sum relu(acc@W1col + den*b1col)*W2col
__global__ void k_node2(const float* __restrict__ as2, const float* __restrict__ ad2,
                        const float* __restrict__ as2r, const float* __restrict__ ad2r, int N) {
    int i = blockIdx.x * blockDim.x + threadIdx.x;
    if (i >= N) return;
    bool rev = (blockIdx.y != 0);

    const float4* base = g_wpack[rev ? 1 : 0];

    float4 a = rev ? g_accr[i] : g_accf[i];
    float den = a.w + 1e-16f;
    float inv = 1.f / den;                                // overlaps the loop below

    float acc = 0.f;
#pragma unroll
    for (int q = 0; q < 4; q++) {
        float4 w0 = base[q], w1 = base[4 + q], w2 = base[8 + q];
        float4 bb = base[12 + q], wo = base[16 + q];
        acc += fmaxf(a.x * w0.x + a.y * w1.x + a.z * w2.x + den * bb.x, 0.f) * wo.x;
        acc += fmaxf(a.x * w0.y + a.y * w1.y + a.z * w2.y + den * bb.y, 0.f) * wo.y;
        acc += fmaxf(a.x * w0.z + a.y * w1.z + a.z * w2.z + den * bb.z, 0.f) * wo.z;
        acc += fmaxf(a.x * w0.w + a.y * w1.w + a.z * w2.w + den * bb.w, 0.f) * wo.w;
    }
    float h2 = acc * inv;

    // write this direction's half of the interleaved per-node pack
    ((float*)&g_H[i])[rev ? 1 : 0] = h2;

    float sum2 = rev ? (__ldg(&as2r[0]) + __ldg(&ad2r[0]))
                     : (__ldg(&as2[0])  + __ldg(&ad2[0]));
    float w = __expf(lrelu(h2 * sum2));
    if (rev) g_nd2r[i] = make_float2(w * h2, w);
    else     g_nd2f[i] = make_float2(w * h2, w);
}

// ---------------- layer 2 edge pass: 2 gathers + 2 REDs per edge, 4 edges/thread ----------------
__global__ void __launch_bounds__(256) k_edge2(const void* __restrict__ ei,
                                               const float* __restrict__ as2,
                                               const float* __restrict__ ad2,
                                               const float* __restrict__ as2r,
                                               const float* __restrict__ ad2r, int E) {
    bool is64 = (g_is64 != 0);
    float a2s = __ldg(&as2[0]),  a2d = __ldg(&ad2[0]);
    float a2sr = __ldg(&as2r[0]), a2dr = __ldg(&ad2r[0]);

    int t = blockIdx.x * blockDim.x + threadIdx.x;
    int j0 = t * EPT2;
    if (j0 >= E) return;
    int n = E - j0; if (n > EPT2) n = EPT2;

    int s[EPT2], d[EPT2];
    if (is64) {
#pragma unroll
        for (int u = 0; u < EPT2; u++) if (u < n) {
            int2 sd = g_sd[j0 + u];
            s[u] = sd.x; d[u] = sd.y;
        }
    } else {
        const int* p = (const int*)ei;
#pragma unroll
        for (int u = 0; u < EPT2; u++) if (u < n) { s[u] = p[j0 + u]; d[u] = p[E + j0 + u]; }
    }

    float2 Hs[EPT2], Hd[EPT2];
#pragma unroll
    for (int u = 0; u < EPT2; u++) if (u < n) {
        Hs[u] = g_H[s[u]];
        Hd[u] = g_H[d[u]];
    }
#pragma unroll
    for (int u = 0; u < EPT2; u++) if (u < n) {
        // forward s->d: score = h2f[s]*as2 + h2f[d]*ad2
        float wf = __expf(lrelu(Hs[u].x * a2s + Hd[u].x * a2d));
        // reverse d->s: score = h2r[d]*as2r + h2r[s]*ad2r
        float wr = __expf(lrelu(Hd[u].y * a2sr + Hs[u].y * a2dr));
        red_add_v2((float*)&g_nd2f[d[u]], wf * Hs[u].x, wf);
        red_add_v2((float*)&g_nd2r[s[u]], wr * Hd[u].y, wr);
    }
}

// ---------------- final combine (2 nodes/thread, vectorized) ----------------
__global__ void k_out(float* __restrict__ out, const float* __restrict__ b2,
                      const float* __restrict__ b2r, int N) {
    int t = blockIdx.x * blockDim.x + threadIdx.x;
    int i = 2 * t;
    if (i >= N) return;
    float bf = __ldg(&b2[0]), br = __ldg(&b2r[0]);
    float4 f = ((const float4*)g_nd2f)[t];   // nd2f[i], nd2f[i+1]
    float4 r = ((const float4*)g_nd2r)[t];
    float o0 = 0.5f * (f.x / (f.y + 1e-16f) + bf + r.x / (r.y + 1e-16f) + br);
    if (i + 1 < N) {
        float o1 = 0.5f * (f.z / (f.w + 1e-16f) + bf + r.z / (r.w + 1e-16f) + br);
        *(float2*)&out[i] = make_float2(o0, o1);
    } else {
        out[i] = o0;
    }
}

extern "C" void kernel_launch(void* const* d_in, const int* in_sizes, int n_in,
                              void* d_out, int out_size) {
    const float* x   = (const float*)d_in[0];
    const void*  ei  = d_in[1];
    const float* W1  = (const float*)d_in[2];
    const float* as1 = (const float*)d_in[3];
    const float* ad1 = (const float*)d_in[4];
    const float* b1  = (const float*)d_in[5];
    const float* W2  = (const float*)d_in[6];
    const float* as2 = (const float*)d_in[7];
    const float* ad2 = (const float*)d_in[8];
    const float* b2  = (const float*)d_in[9];
    const float* W1r  = (const float*)d_in[10];
    const float* as1r = (const float*)d_in[11];
    const float* ad1r = (const float*)d_in[12];
    const float* b1r  = (const float*)d_in[13];
    const float* W2r  = (const float*)d_in[14];
    const float* as2r = (const float*)d_in[15];
    const float* ad2r = (const float*)d_in[16];
    const float* b2r  = (const float*)d_in[17];

    int N = in_sizes[0] / 3;
    int E = in_sizes[1] / 2;

    const int TB = 256;
    int nbN = (N + TB - 1) / TB;
    int nbE = (E + TB * EPT - 1) / (TB * EPT);
    int nbE2 = (E + TB * EPT2 - 1) / (TB * EPT2);
    int nbO = (N + TB * 2 - 1) / (TB * 2);

    dim3 grid2(nbN, 2);

    k_pre<<<1, 192>>>(W1, as1, ad1, W1r, as1r, ad1r, b1, W2, b1r, W2r, (const int*)ei);
    k_node1<<<nbN, TB>>>(x, N);
    k_edge1<<<nbE, TB>>>(ei, E);
    k_node2<<<grid2, TB>>>(as2, ad2, as2r, ad2r, N);
    k_edge2<<<nbE2, TB>>>(ei, as2, ad2, as2r, ad2r, E);
    k_out<<<nbO, TB>>>((float*)d_out, b2, b2r, N);
}